// round 7
// baseline (speedup 1.0000x reference)
#include <cuda_runtime.h>

// EgoAttentionNetwork: B=8192, E=64, F_IN=7, D=64, H=4, HD=16
// Round-6: weights for the big GEMMs live in __constant__ memory (uniform
// constant port, not L1). GEMMs are lane=entity / warp=8-features so weight
// addresses are warp-uniform (LDCU) and activations are 1 conflict-free
// LDS.32 per k. V is kept in registers through softmax; K is never stored.

typedef unsigned long long u64;

#define NTHR 256
#define FULLMASK 0xffffffffu
#define HST 36      // hT col stride (one 32-entity chunk + pad)
#define AST2 72     // aT col stride (two chunks of 36)

__constant__ float cW1[4096];   // oth_w1 [k][d]
__constant__ float cWk[4096];   // Wk     [k][d]
__constant__ float cWv[4096];   // Wv     [k][d]
__constant__ float cW0[448];    // oth_w0 [f][d]
__constant__ float cB0[64];
__constant__ float cB1[64];

static __device__ __forceinline__ u64 fma2(u64 a, u64 b, u64 c) {
    u64 d;
    asm("fma.rn.f32x2 %0, %1, %2, %3;" : "=l"(d) : "l"(a), "l"(b), "l"(c));
    return d;
}
static __device__ __forceinline__ u64 add2(u64 a, u64 b) {
    u64 d;
    asm("add.rn.f32x2 %0, %1, %2;" : "=l"(d) : "l"(a), "l"(b));
    return d;
}
static __device__ __forceinline__ u64 mul2(u64 a, u64 b) {
    u64 d;
    asm("mul.rn.f32x2 %0, %1, %2;" : "=l"(d) : "l"(a), "l"(b));
    return d;
}
static __device__ __forceinline__ u64 dup2(float x) {
    u64 r;
    asm("mov.b64 %0, {%1, %1};" : "=l"(r) : "f"(x));
    return r;
}
static __device__ __forceinline__ float2 unpack2(u64 v) {
    float2 r;
    asm("mov.b64 {%0, %1}, %2;" : "=f"(r.x), "=f"(r.y) : "l"(v));
    return r;
}

struct __align__(16) SmemT {
    float hT[64 * HST];    // layer0 out, one chunk at a time (9216 B)
    float aT[64 * AST2];   // input_all^T, up to two chunks   (18432 B)
    float sXT[7 * 68];     // x transposed [f][e]             (1904 B)
    float h0[64];
    float sEgo[64];
    float sQ[64];
    float sO[64];
    float sSp[8 * AST2];   // per-warp score partials         (2304 B)
    float sP[4 * AST2];    // probs per head                  (1152 B)
    int   sIdx[64];
    int   nOth, uniformF, egoAct;
};

__global__ void __launch_bounds__(NTHR, 4)
ego_attn_kernel(const float* __restrict__ x,
                const float* __restrict__ ego_w0, const float* __restrict__ ego_b0,
                const float* __restrict__ ego_w1, const float* __restrict__ ego_b1,
                const float* __restrict__ Wq, const float* __restrict__ Wc,
                float* __restrict__ out)
{
    __shared__ SmemT s;
    const int tid = threadIdx.x;
    const int lane = tid & 31;
    const int w = tid >> 5;
    const int d0 = w * 8;          // this warp's 8 output features
    const int b = blockIdx.x;
    const float* xb = x + b * 448;

    // ---- PH1: load x transposed ----
    for (int idx = tid; idx < 448; idx += NTHR) {
        int e = idx / 7, f = idx - e * 7;
        s.sXT[f * 68 + e] = __ldg(xb + idx);
    }
    __syncthreads();

    // ---- PH2: compaction (warp0) | ego layer0 (warp1) ----
    if (w == 0) {
        int egoA = (s.sXT[0] >= 0.5f) ? 1 : 0;
        unsigned m1 = __ballot_sync(FULLMASK, (lane >= 1) && (s.sXT[lane] >= 0.5f));
        unsigned m2 = __ballot_sync(FULLMASK, s.sXT[lane + 32] >= 0.5f);
        int cnt = __popc(m1) + __popc(m2);
        unsigned lmask = (1u << lane) - 1u;
        if (cnt == 0 && !egoA) {
            s.sIdx[lane] = lane + 1;
            if (lane < 31) s.sIdx[lane + 32] = lane + 33;
            if (lane == 0) { s.nOth = 63; s.uniformF = 1; s.egoAct = egoA; }
        } else {
            if ((lane >= 1) && (m1 >> lane & 1u))
                s.sIdx[__popc(m1 & lmask)] = lane;
            if (m2 >> lane & 1u)
                s.sIdx[__popc(m1) + __popc(m2 & lmask)] = lane + 32;
            if (lane == 0) { s.nOth = cnt; s.uniformF = 0; s.egoAct = egoA; }
        }
    } else if (w == 1) {
        #pragma unroll
        for (int r = 0; r < 2; r++) {
            int d = lane + r * 32;
            float acc = __ldg(ego_b0 + d);
            #pragma unroll
            for (int f = 0; f < 7; f++)
                acc += s.sXT[f * 68] * __ldg(ego_w0 + f * 64 + d);
            s.h0[d] = fmaxf(acc, 0.f);
        }
    }
    __syncthreads();

    const int nOth = s.nOth;
    const int uniformF = s.uniformF;
    const int egoAct = s.egoAct;
    const int cEgo = nOth;
    const int nTot = nOth + 1;
    const int nchunks = (nTot > 32) ? 2 : 1;

    // ---- per-chunk: layer0 (warps 2-7) / ego-l1 (warps 0-1), then layer1 ----
    for (int c = 0; c < nchunks; c++) {
        if (w >= 2) {
            for (int t = w - 2; t < 8; t += 6) {
                const int dd = t * 8;
                const int ig = c * 32 + lane;
                const bool val = (ig < nOth);
                const int e = val ? s.sIdx[ig] : 0;
                const ulonglong2* bb = reinterpret_cast<const ulonglong2*>(&cB0[dd]);
                ulonglong2 b01 = bb[0], b23 = bb[1];
                u64 acc[4] = {b01.x, b01.y, b23.x, b23.y};
                #pragma unroll
                for (int f = 0; f < 7; f++) {
                    u64 xd = dup2(s.sXT[f * 68 + e]);
                    const ulonglong2* cw =
                        reinterpret_cast<const ulonglong2*>(&cW0[f * 64 + dd]);
                    ulonglong2 wA = cw[0], wB = cw[1];
                    acc[0] = fma2(xd, wA.x, acc[0]);
                    acc[1] = fma2(xd, wA.y, acc[1]);
                    acc[2] = fma2(xd, wB.x, acc[2]);
                    acc[3] = fma2(xd, wB.y, acc[3]);
                }
                #pragma unroll
                for (int j = 0; j < 4; j++) {
                    float2 p = unpack2(acc[j]);
                    s.hT[(dd + 2 * j) * HST + lane]     = val ? fmaxf(p.x, 0.f) : 0.f;
                    s.hT[(dd + 2 * j + 1) * HST + lane] = val ? fmaxf(p.y, 0.f) : 0.f;
                }
            }
        } else if (c == 0 && tid < 64) {
            const int d = tid;
            float a0 = __ldg(ego_b1 + d), a1 = 0.f, a2 = 0.f, a3 = 0.f;
            #pragma unroll 8
            for (int k = 0; k < 64; k += 4) {
                a0 += s.h0[k]     * __ldg(ego_w1 + (k)     * 64 + d);
                a1 += s.h0[k + 1] * __ldg(ego_w1 + (k + 1) * 64 + d);
                a2 += s.h0[k + 2] * __ldg(ego_w1 + (k + 2) * 64 + d);
                a3 += s.h0[k + 3] * __ldg(ego_w1 + (k + 3) * 64 + d);
            }
            s.sEgo[d] = fmaxf((a0 + a1) + (a2 + a3), 0.f);
        }
        __syncthreads();

        // layer1 GEMM: all 8 warps, lane=entity, 8 features each
        {
            const ulonglong2* bb = reinterpret_cast<const ulonglong2*>(&cB1[d0]);
            ulonglong2 b01 = bb[0], b23 = bb[1];
            u64 acc[4] = {b01.x, b01.y, b23.x, b23.y};
            #pragma unroll 4
            for (int k = 0; k < 64; k++) {
                u64 ad = dup2(s.hT[k * HST + lane]);
                const ulonglong2* cw =
                    reinterpret_cast<const ulonglong2*>(&cW1[k * 64 + d0]);
                ulonglong2 wA = cw[0], wB = cw[1];
                acc[0] = fma2(ad, wA.x, acc[0]);
                acc[1] = fma2(ad, wA.y, acc[1]);
                acc[2] = fma2(ad, wB.x, acc[2]);
                acc[3] = fma2(ad, wB.y, acc[3]);
            }
            const int gcol = c * 32 + lane;
            const bool isEgo = (gcol == cEgo);
            #pragma unroll
            for (int j = 0; j < 4; j++) {
                float2 p = unpack2(acc[j]);
                float v0 = fmaxf(p.x, 0.f), v1 = fmaxf(p.y, 0.f);
                if (isEgo) { v0 = s.sEgo[d0 + 2 * j]; v1 = s.sEgo[d0 + 2 * j + 1]; }
                s.aT[(d0 + 2 * j) * AST2 + c * 36 + lane]     = v0;
                s.aT[(d0 + 2 * j + 1) * AST2 + c * 36 + lane] = v1;
            }
        }
        __syncthreads();
    }

    // ---- q = Wq^T sEgo (threads 0-63) ----
    if (tid < 64) {
        const int d = tid;
        float a0 = 0.f, a1 = 0.f, a2 = 0.f, a3 = 0.f;
        #pragma unroll 8
        for (int k = 0; k < 64; k += 4) {
            a0 += s.sEgo[k]     * __ldg(Wq + (k)     * 64 + d);
            a1 += s.sEgo[k + 1] * __ldg(Wq + (k + 1) * 64 + d);
            a2 += s.sEgo[k + 2] * __ldg(Wq + (k + 2) * 64 + d);
            a3 += s.sEgo[k + 3] * __ldg(Wq + (k + 3) * 64 + d);
        }
        s.sQ[d] = (a0 + a1) + (a2 + a3);
    }
    __syncthreads();

    // ---- PH5: K (+V fused on fast path); scores to sSp ----
    u64 vacc[4] = {0, 0, 0, 0};
    if (nchunks == 1) {
        u64 kacc[4] = {0, 0, 0, 0};
        #pragma unroll 4
        for (int k = 0; k < 64; k++) {
            u64 ad = dup2(s.aT[k * AST2 + lane]);
            const ulonglong2* ck = reinterpret_cast<const ulonglong2*>(&cWk[k * 64 + d0]);
            const ulonglong2* cv = reinterpret_cast<const ulonglong2*>(&cWv[k * 64 + d0]);
            ulonglong2 kA = ck[0], kB = ck[1];
            ulonglong2 vA = cv[0], vB = cv[1];
            kacc[0] = fma2(ad, kA.x, kacc[0]);
            kacc[1] = fma2(ad, kA.y, kacc[1]);
            kacc[2] = fma2(ad, kB.x, kacc[2]);
            kacc[3] = fma2(ad, kB.y, kacc[3]);
            vacc[0] = fma2(ad, vA.x, vacc[0]);
            vacc[1] = fma2(ad, vA.y, vacc[1]);
            vacc[2] = fma2(ad, vB.x, vacc[2]);
            vacc[3] = fma2(ad, vB.y, vacc[3]);
        }
        u64 t = 0;
        #pragma unroll
        for (int j = 0; j < 4; j++) {
            u64 qp = *reinterpret_cast<const u64*>(&s.sQ[d0 + 2 * j]);
            t = fma2(kacc[j], qp, t);
        }
        float2 tf = unpack2(t);
        s.sSp[w * AST2 + lane] = tf.x + tf.y;
    } else {
        for (int c = 0; c < 2; c++) {
            u64 kacc[4] = {0, 0, 0, 0};
            #pragma unroll 4
            for (int k = 0; k < 64; k++) {
                u64 ad = dup2(s.aT[k * AST2 + c * 36 + lane]);
                const ulonglong2* ck =
                    reinterpret_cast<const ulonglong2*>(&cWk[k * 64 + d0]);
                ulonglong2 kA = ck[0], kB = ck[1];
                kacc[0] = fma2(ad, kA.x, kacc[0]);
                kacc[1] = fma2(ad, kA.y, kacc[1]);
                kacc[2] = fma2(ad, kB.x, kacc[2]);
                kacc[3] = fma2(ad, kB.y, kacc[3]);
            }
            u64 t = 0;
            #pragma unroll
            for (int j = 0; j < 4; j++) {
                u64 qp = *reinterpret_cast<const u64*>(&s.sQ[d0 + 2 * j]);
                t = fma2(kacc[j], qp, t);
            }
            float2 tf = unpack2(t);
            s.sSp[w * AST2 + c * 36 + lane] = tf.x + tf.y;
        }
    }
    __syncthreads();

    // ---- PH6: softmax (warps 0-3, head = warp) ----
    if (w < 4) {
        const int h = w;
        float sc0, sc1 = -1e30f;
        {
            float raw = s.sSp[(2 * h) * AST2 + lane] + s.sSp[(2 * h + 1) * AST2 + lane];
            bool act = uniformF ? (lane < nTot)
                                : ((lane < nOth) || (lane == cEgo && egoAct));
            sc0 = act ? raw * 0.25f : -1e30f;
        }
        if (nchunks == 2) {
            float raw = s.sSp[(2 * h) * AST2 + 36 + lane]
                      + s.sSp[(2 * h + 1) * AST2 + 36 + lane];
            int col = 32 + lane;
            bool act = uniformF ? (col < nTot)
                                : ((col < nOth) || (col == cEgo && egoAct));
            sc1 = act ? raw * 0.25f : -1e30f;
        }
        if (uniformF) {
            const float p = 1.0f / 64.0f;
            s.sP[h * AST2 + lane] = p;
            if (nchunks == 2) s.sP[h * AST2 + 36 + lane] = p;
        } else {
            float m = fmaxf(sc0, sc1);
            #pragma unroll
            for (int off = 16; off; off >>= 1)
                m = fmaxf(m, __shfl_xor_sync(FULLMASK, m, off));
            float e0 = __expf(sc0 - m);
            float e1 = (nchunks == 2) ? __expf(sc1 - m) : 0.f;
            float sum = e0 + e1;
            #pragma unroll
            for (int off = 16; off; off >>= 1)
                sum += __shfl_xor_sync(FULLMASK, sum, off);
            float inv = 1.0f / sum;
            s.sP[h * AST2 + lane] = e0 * inv;
            if (nchunks == 2) s.sP[h * AST2 + 36 + lane] = e1 * inv;
        }
    }
    __syncthreads();

    // ---- PH7: out = sum_e p[e] * V[e][d] via shfl butterfly ----
    {
        const int h2 = w >> 1;
        u64 r[4];
        if (nchunks == 1) {
            u64 pd = dup2(s.sP[h2 * AST2 + lane]);
            #pragma unroll
            for (int j = 0; j < 4; j++) r[j] = mul2(pd, vacc[j]);
        } else {
            r[0] = r[1] = r[2] = r[3] = 0;
            for (int c = 0; c < 2; c++) {
                u64 va[4] = {0, 0, 0, 0};
                #pragma unroll 4
                for (int k = 0; k < 64; k++) {
                    u64 ad = dup2(s.aT[k * AST2 + c * 36 + lane]);
                    const ulonglong2* cv =
                        reinterpret_cast<const ulonglong2*>(&cWv[k * 64 + d0]);
                    ulonglong2 vA = cv[0], vB = cv[1];
                    va[0] = fma2(ad, vA.x, va[0]);
                    va[1] = fma2(ad, vA.y, va[1]);
                    va[2] = fma2(ad, vB.x, va[2]);
                    va[3] = fma2(ad, vB.y, va[3]);
                }
                u64 pd = dup2(s.sP[h2 * AST2 + c * 36 + lane]);
                #pragma unroll
                for (int j = 0; j < 4; j++) r[j] = fma2(pd, va[j], r[j]);
            }
        }
        #pragma unroll
        for (int off = 1; off < 32; off <<= 1) {
            #pragma unroll
            for (int j = 0; j < 4; j++)
                r[j] = add2(r[j], __shfl_xor_sync(FULLMASK, r[j], off));
        }
        if (lane == 0) {
            #pragma unroll
            for (int j = 0; j < 4; j++) {
                float2 p = unpack2(r[j]);
                s.sO[d0 + 2 * j]     = p.x;
                s.sO[d0 + 2 * j + 1] = p.y;
            }
        }
    }
    __syncthreads();

    // ---- PH8: epilogue (out @ Wc + ego) * 0.5 ----
    if (tid < 64) {
        const int d = tid;
        float a0 = 0.f, a1 = 0.f, a2 = 0.f, a3 = 0.f;
        #pragma unroll 8
        for (int k = 0; k < 64; k += 4) {
            a0 += s.sO[k]     * __ldg(Wc + (k)     * 64 + d);
            a1 += s.sO[k + 1] * __ldg(Wc + (k + 1) * 64 + d);
            a2 += s.sO[k + 2] * __ldg(Wc + (k + 2) * 64 + d);
            a3 += s.sO[k + 3] * __ldg(Wc + (k + 3) * 64 + d);
        }
        out[b * 64 + d] = (((a0 + a1) + (a2 + a3)) + s.sEgo[d]) * 0.5f;
    }
}

extern "C" void kernel_launch(void* const* d_in, const int* in_sizes, int n_in,
                              void* d_out, int out_size) {
    (void)in_sizes; (void)n_in; (void)out_size;
    const float* x      = (const float*)d_in[0];
    const float* ego_w0 = (const float*)d_in[1];
    const float* ego_b0 = (const float*)d_in[2];
    const float* ego_w1 = (const float*)d_in[3];
    const float* ego_b1 = (const float*)d_in[4];
    const float* oth_w0 = (const float*)d_in[5];
    const float* oth_b0 = (const float*)d_in[6];
    const float* oth_w1 = (const float*)d_in[7];
    const float* oth_b1 = (const float*)d_in[8];
    const float* Wk     = (const float*)d_in[9];
    const float* Wv     = (const float*)d_in[10];
    const float* Wq     = (const float*)d_in[11];
    const float* Wc     = (const float*)d_in[12];
    float* out = (float*)d_out;

    // Stage GEMM weights into constant memory (device-to-device async copies;
    // graph-capturable memcpy nodes, no allocation).
    cudaMemcpyToSymbolAsync(cW1, oth_w1, 4096 * sizeof(float), 0,
                            cudaMemcpyDeviceToDevice);
    cudaMemcpyToSymbolAsync(cWk, Wk, 4096 * sizeof(float), 0,
                            cudaMemcpyDeviceToDevice);
    cudaMemcpyToSymbolAsync(cWv, Wv, 4096 * sizeof(float), 0,
                            cudaMemcpyDeviceToDevice);
    cudaMemcpyToSymbolAsync(cW0, oth_w0, 448 * sizeof(float), 0,
                            cudaMemcpyDeviceToDevice);
    cudaMemcpyToSymbolAsync(cB0, oth_b0, 64 * sizeof(float), 0,
                            cudaMemcpyDeviceToDevice);
    cudaMemcpyToSymbolAsync(cB1, oth_b1, 64 * sizeof(float), 0,
                            cudaMemcpyDeviceToDevice);

    ego_attn_kernel<<<8192, NTHR>>>(x, ego_w0, ego_b0, ego_w1, ego_b1,
                                    Wq, Wc, out);
}

// round 8
// speedup vs baseline: 5.8839x; 5.8839x over previous
#include <cuda_runtime.h>
#include <cuda_fp16.h>

// EgoAttentionNetwork: B=8192, E=64, F_IN=7, D=64, H=4, HD=16
// Round-7 = Round-4 design (best: 172.5us) + fp16 weight streams for the
// wavefront-dominant GEMMs (oth_w0, oth_w1, Wk, Wv), converted once per
// replay by a prep kernel into __device__ scratch. Accumulation stays fp32.
// Ego path / Wq / Wc / biases / x remain fp32 (precision headroom).

typedef unsigned long long u64;

#define AST 68
#define NTHR 256
#define FULLMASK 0xffffffffu

__device__ __half dW0h[448];    // oth_w0 [f][d]
__device__ __half dW1h[4096];   // oth_w1 [k][d]
__device__ __half dWkh[4096];   // Wk     [k][d]
__device__ __half dWvh[4096];   // Wv     [k][d]

static __device__ __forceinline__ u64 fma2(u64 a, u64 b, u64 c) {
    u64 d;
    asm("fma.rn.f32x2 %0, %1, %2, %3;" : "=l"(d) : "l"(a), "l"(b), "l"(c));
    return d;
}
static __device__ __forceinline__ u64 dup2(float x) {
    u64 r;
    asm("mov.b64 %0, {%1, %1};" : "=l"(r) : "f"(x));
    return r;
}
static __device__ __forceinline__ float2 unpack2(u64 v) {
    float2 r;
    asm("mov.b64 {%0, %1}, %2;" : "=f"(r.x), "=f"(r.y) : "l"(v));
    return r;
}
static __device__ __forceinline__ void loadA(const float* p, u64& a, u64& b) {
    float4 v = *reinterpret_cast<const float4*>(p);
    asm("mov.b64 %0, {%1, %2};" : "=l"(a) : "f"(v.x), "f"(v.y));
    asm("mov.b64 %0, {%1, %2};" : "=l"(b) : "f"(v.z), "f"(v.w));
}

__global__ void prep_weights(const float* __restrict__ oth_w0,
                             const float* __restrict__ oth_w1,
                             const float* __restrict__ Wk,
                             const float* __restrict__ Wv)
{
    const int i = blockIdx.x * 256 + threadIdx.x;
    if (i < 448)  dW0h[i] = __float2half(__ldg(oth_w0 + i));
    if (i < 4096) {
        dW1h[i] = __float2half(__ldg(oth_w1 + i));
        dWkh[i] = __float2half(__ldg(Wk + i));
        dWvh[i] = __float2half(__ldg(Wv + i));
    }
}

struct __align__(16) SmemT {
    float hT[64 * AST];   // hidden^T; reused as V^T after layer1
    float aT[64 * AST];   // input_all^T
    float sX[64 * 8];     // raw x rows (padded)
    float h0[64];
    float sEgo[64];
    float sQ[64];
    float sO[64];
    float sS[256];
    float sP[256];
    int   sIdx[64];
    int   nOth, uniformF, egoAct;
};

__global__ void __launch_bounds__(NTHR, 4)
ego_attn_kernel(const float* __restrict__ x,
                const float* __restrict__ ego_w0, const float* __restrict__ ego_b0,
                const float* __restrict__ ego_w1, const float* __restrict__ ego_b1,
                const float* __restrict__ oth_b0, const float* __restrict__ oth_b1,
                const float* __restrict__ Wq, const float* __restrict__ Wc,
                float* __restrict__ out)
{
    __shared__ SmemT s;
    const int tid = threadIdx.x;
    const int b = blockIdx.x;
    const int dt2 = tid & 31;             // 32 d-tiles of 2 features
    const int d0 = dt2 * 2;
    const int etw = tid >> 5;
    const int etr = (etw + (b & 7)) & 7;  // rotated entity tile (4 entities)
    const float* xb = x + b * 448;
    const __half2* W0h2 = reinterpret_cast<const __half2*>(dW0h);
    const __half2* W1h2 = reinterpret_cast<const __half2*>(dW1h);
    const __half2* Wkh2 = reinterpret_cast<const __half2*>(dWkh);
    const __half2* Wvh2 = reinterpret_cast<const __half2*>(dWvh);

    // ---- PH1: load x, init scores ----
    for (int idx = tid; idx < 448; idx += NTHR) {
        int e = idx / 7, f = idx % 7;
        s.sX[e * 8 + f] = __ldg(xb + idx);
    }
    s.sS[tid] = -1e30f;
    __syncthreads();

    // ---- PH2: compaction (warp0) | ego layer0 (warp1) ----
    if (tid < 32) {
        const int lane = tid;
        int egoA = (s.sX[0] >= 0.5f) ? 1 : 0;
        unsigned m1 = __ballot_sync(FULLMASK, (lane >= 1) && (s.sX[lane * 8] >= 0.5f));
        unsigned m2 = __ballot_sync(FULLMASK, s.sX[(lane + 32) * 8] >= 0.5f);
        int cnt = __popc(m1) + __popc(m2);
        unsigned lmask = (1u << lane) - 1u;
        if (cnt == 0 && !egoA) {
            // all masked -> uniform softmax over all 64 entities
            s.sIdx[lane] = lane + 1;
            if (lane < 31) s.sIdx[lane + 32] = lane + 33;
            if (lane == 0) { s.nOth = 63; s.uniformF = 1; s.egoAct = egoA; }
        } else {
            if ((lane >= 1) && (m1 >> lane & 1u))
                s.sIdx[__popc(m1 & lmask)] = lane;
            if (m2 >> lane & 1u)
                s.sIdx[__popc(m1) + __popc(m2 & lmask)] = lane + 32;
            if (lane == 0) { s.nOth = cnt; s.uniformF = 0; s.egoAct = egoA; }
        }
    } else if (tid < 64) {
        const int lane = tid - 32;
        #pragma unroll
        for (int r = 0; r < 2; r++) {
            int d = lane + r * 32;
            float acc = __ldg(ego_b0 + d);
            #pragma unroll
            for (int f = 0; f < 7; f++)
                acc += s.sX[f] * __ldg(ego_w0 + f * 64 + d);
            s.h0[d] = fmaxf(acc, 0.f);
        }
    }
    __syncthreads();

    const int nOth = s.nOth;
    const int uniformF = s.uniformF;
    const int egoAct = s.egoAct;
    const int cEgo = nOth;
    const int nTot = nOth + 1;
    int PADMAX = (nTot + 3) & ~3; if (PADMAX > 64) PADMAX = 64;
    const int nTiles = PADMAX >> 2;
    const int npass = (PADMAX + 31) >> 5;

    // ---- PH3: others layer0 (192 thr, fp16 weights) | ego layer1 ----
    if (tid < 192) {
        const int total = nOth * 32;
        for (int idx = tid; idx < total; idx += 192) {
            int i = idx >> 5, dd = (idx & 31) * 2;
            int e = s.sIdx[i];
            const float* xr = s.sX + e * 8;
            float2 bb = *reinterpret_cast<const float2*>(oth_b0 + dd);
            float ax = bb.x, ay = bb.y;
            #pragma unroll
            for (int f = 0; f < 7; f++) {
                float2 w = __half22float2(W0h2[f * 32 + (dd >> 1)]);
                float xv = xr[f];
                ax += xv * w.x; ay += xv * w.y;
            }
            s.hT[dd * AST + i]       = fmaxf(ax, 0.f);
            s.hT[(dd + 1) * AST + i] = fmaxf(ay, 0.f);
        }
    } else {
        const int d = tid - 192;
        float a0 = __ldg(ego_b1 + d), a1 = 0.f, a2 = 0.f, a3 = 0.f;
        #pragma unroll 8
        for (int k = 0; k < 64; k += 4) {
            a0 += s.h0[k]     * __ldg(ego_w1 + (k)     * 64 + d);
            a1 += s.h0[k + 1] * __ldg(ego_w1 + (k + 1) * 64 + d);
            a2 += s.h0[k + 2] * __ldg(ego_w1 + (k + 2) * 64 + d);
            a3 += s.h0[k + 3] * __ldg(ego_w1 + (k + 3) * 64 + d);
        }
        s.sEgo[d] = fmaxf((a0 + a1) + (a2 + a3), 0.f);
    }
    if (tid < 64) {
        for (int c = nOth; c < PADMAX; c++) s.hT[tid * AST + c] = 0.f;
    }
    __syncthreads();

    // ---- PH4: layer1 GEMM hT->aT (fp16 weights); free warps: q ----
    for (int ep = 0; ep < npass; ep++) {
        const int e0 = ep * 32 + etr * 4;
        if (e0 < PADMAX) {
            u64 a00 = 0, a01 = 0, a10 = 0, a11 = 0;
            #pragma unroll 8
            for (int k = 0; k < 64; k++) {
                u64 p01, p23; loadA(s.hT + k * AST + e0, p01, p23);
                float2 w = __half22float2(W1h2[k * 32 + dt2]);
                u64 wx = dup2(w.x), wy = dup2(w.y);
                a00 = fma2(p01, wx, a00);  a01 = fma2(p23, wx, a01);
                a10 = fma2(p01, wy, a10);  a11 = fma2(p23, wy, a11);
            }
            float b0v = __ldg(oth_b1 + d0);
            float b1v = __ldg(oth_b1 + d0 + 1);
            float2 c0 = unpack2(a00), c1 = unpack2(a01);
            float2 c2 = unpack2(a10), c3 = unpack2(a11);
            float r0[4] = { fmaxf(c0.x + b0v, 0.f), fmaxf(c0.y + b0v, 0.f),
                            fmaxf(c1.x + b0v, 0.f), fmaxf(c1.y + b0v, 0.f) };
            float r1[4] = { fmaxf(c2.x + b1v, 0.f), fmaxf(c2.y + b1v, 0.f),
                            fmaxf(c3.x + b1v, 0.f), fmaxf(c3.y + b1v, 0.f) };
            const int patch = cEgo - e0;
            if (patch >= 0 && patch < 4) {
                r0[patch] = s.sEgo[d0];
                r1[patch] = s.sEgo[d0 + 1];
            }
            *reinterpret_cast<float4*>(s.aT + d0 * AST + e0) =
                make_float4(r0[0], r0[1], r0[2], r0[3]);
            *reinterpret_cast<float4*>(s.aT + (d0 + 1) * AST + e0) =
                make_float4(r1[0], r1[1], r1[2], r1[3]);
        }
    }
    const bool canFreeQ = (nTiles <= 6);
    if (canFreeQ && etr >= nTiles && (etr - nTiles) < 2) {
        const int d = (etr - nTiles) * 32 + dt2;
        float a0 = 0.f, a1 = 0.f, a2 = 0.f, a3 = 0.f;
        #pragma unroll 8
        for (int k = 0; k < 64; k += 4) {
            a0 += s.sEgo[k]     * __ldg(Wq + (k)     * 64 + d);
            a1 += s.sEgo[k + 1] * __ldg(Wq + (k + 1) * 64 + d);
            a2 += s.sEgo[k + 2] * __ldg(Wq + (k + 2) * 64 + d);
            a3 += s.sEgo[k + 3] * __ldg(Wq + (k + 3) * 64 + d);
        }
        s.sQ[d] = (a0 + a1) + (a2 + a3);
    }
    __syncthreads();
    if (!canFreeQ) {
        if (tid < 64) {
            const int d = tid;
            float a0 = 0.f, a1 = 0.f, a2 = 0.f, a3 = 0.f;
            #pragma unroll 8
            for (int k = 0; k < 64; k += 4) {
                a0 += s.sEgo[k]     * __ldg(Wq + (k)     * 64 + d);
                a1 += s.sEgo[k + 1] * __ldg(Wq + (k + 1) * 64 + d);
                a2 += s.sEgo[k + 2] * __ldg(Wq + (k + 2) * 64 + d);
                a3 += s.sEgo[k + 3] * __ldg(Wq + (k + 3) * 64 + d);
            }
            s.sQ[d] = (a0 + a1) + (a2 + a3);
        }
        __syncthreads();
    }

    // ---- PH5: fused K+V GEMM (fp16 weights); scores via shfl; V^T -> hT ----
    for (int ep = 0; ep < npass; ep++) {
        const int e0 = ep * 32 + etr * 4;
        if (e0 < PADMAX) {
            u64 k00 = 0, k01 = 0, k10 = 0, k11 = 0;
            u64 v00 = 0, v01 = 0, v10 = 0, v11 = 0;
            #pragma unroll 4
            for (int k = 0; k < 64; k++) {
                u64 p01, p23; loadA(s.aT + k * AST + e0, p01, p23);
                float2 wk = __half22float2(Wkh2[k * 32 + dt2]);
                float2 wv = __half22float2(Wvh2[k * 32 + dt2]);
                u64 kx = dup2(wk.x), ky = dup2(wk.y);
                u64 vx = dup2(wv.x), vy = dup2(wv.y);
                k00 = fma2(p01, kx, k00);  k01 = fma2(p23, kx, k01);
                k10 = fma2(p01, ky, k10);  k11 = fma2(p23, ky, k11);
                v00 = fma2(p01, vx, v00);  v01 = fma2(p23, vx, v01);
                v10 = fma2(p01, vy, v10);  v11 = fma2(p23, vy, v11);
            }
            u64 q0 = dup2(s.sQ[d0]), q1 = dup2(s.sQ[d0 + 1]);
            u64 s01 = fma2(k00, q0, (u64)0), s23 = fma2(k01, q0, (u64)0);
            s01 = fma2(k10, q1, s01);        s23 = fma2(k11, q1, s23);
            float2 f01 = unpack2(s01), f23 = unpack2(s23);
            float sc0 = f01.x, sc1 = f01.y, sc2 = f23.x, sc3 = f23.y;
            #pragma unroll
            for (int o = 1; o < 8; o <<= 1) {
                sc0 += __shfl_xor_sync(FULLMASK, sc0, o);
                sc1 += __shfl_xor_sync(FULLMASK, sc1, o);
                sc2 += __shfl_xor_sync(FULLMASK, sc2, o);
                sc3 += __shfl_xor_sync(FULLMASK, sc3, o);
            }
            if ((dt2 & 7) == 0) {
                const int h = dt2 >> 3;
                float scv[4] = {sc0, sc1, sc2, sc3};
                #pragma unroll
                for (int m = 0; m < 4; m++) {
                    int col = e0 + m;
                    bool act = uniformF ? (col < nTot)
                                        : ((col < nOth) || (col == cEgo && egoAct));
                    s.sS[h * 64 + col] = act ? scv[m] * 0.25f : -1e30f;
                }
            }
            float2 va = unpack2(v00), vb = unpack2(v01);
            *reinterpret_cast<float4*>(s.hT + d0 * AST + e0) =
                make_float4(va.x, va.y, vb.x, vb.y);
            float2 vc = unpack2(v10), vd = unpack2(v11);
            *reinterpret_cast<float4*>(s.hT + (d0 + 1) * AST + e0) =
                make_float4(vc.x, vc.y, vd.x, vd.y);
        }
    }
    __syncthreads();

    // ---- PH6: softmax per head (warps 0-3) ----
    if (tid < 128) {
        const int h = tid >> 5, lane = tid & 31;
        if (uniformF) {
            const float p = 1.0f / 64.0f;
            s.sP[h * 64 + lane] = p;
            s.sP[h * 64 + lane + 32] = p;
        } else {
            float s0 = s.sS[h * 64 + lane];
            float s1 = s.sS[h * 64 + lane + 32];
            float m = fmaxf(s0, s1);
            #pragma unroll
            for (int off = 16; off; off >>= 1)
                m = fmaxf(m, __shfl_xor_sync(FULLMASK, m, off));
            float e0v = __expf(s0 - m);
            float e1v = __expf(s1 - m);
            float sum = e0v + e1v;
            #pragma unroll
            for (int off = 16; off; off >>= 1)
                sum += __shfl_xor_sync(FULLMASK, sum, off);
            float inv = 1.0f / sum;
            s.sP[h * 64 + lane] = e0v * inv;
            s.sP[h * 64 + lane + 32] = e1v * inv;
        }
    }
    __syncthreads();

    // ---- PH7: attention-weighted sum from V^T ----
    if (tid < 64) {
        const int d = tid, h = d >> 4;
        const float* pr = s.sP + h * 64;
        const float* vr = s.hT + d * AST;
        float a0 = 0.f, a1 = 0.f;
        for (int i = 0; i < PADMAX; i += 4) {
            float4 v = *reinterpret_cast<const float4*>(vr + i);
            a0 += pr[i] * v.x + pr[i + 1] * v.y;
            a1 += pr[i + 2] * v.z + pr[i + 3] * v.w;
        }
        s.sO[d] = a0 + a1;
    }
    __syncthreads();

    // ---- PH8: epilogue (out @ Wc + ego) * 0.5 ----
    if (tid < 64) {
        const int d = tid;
        float a0 = 0.f, a1 = 0.f, a2 = 0.f, a3 = 0.f;
        #pragma unroll 8
        for (int k = 0; k < 64; k += 4) {
            a0 += s.sO[k]     * __ldg(Wc + (k)     * 64 + d);
            a1 += s.sO[k + 1] * __ldg(Wc + (k + 1) * 64 + d);
            a2 += s.sO[k + 2] * __ldg(Wc + (k + 2) * 64 + d);
            a3 += s.sO[k + 3] * __ldg(Wc + (k + 3) * 64 + d);
        }
        out[b * 64 + d] = (((a0 + a1) + (a2 + a3)) + s.sEgo[d]) * 0.5f;
    }
}

extern "C" void kernel_launch(void* const* d_in, const int* in_sizes, int n_in,
                              void* d_out, int out_size) {
    (void)in_sizes; (void)n_in; (void)out_size;
    const float* x      = (const float*)d_in[0];
    const float* ego_w0 = (const float*)d_in[1];
    const float* ego_b0 = (const float*)d_in[2];
    const float* ego_w1 = (const float*)d_in[3];
    const float* ego_b1 = (const float*)d_in[4];
    const float* oth_w0 = (const float*)d_in[5];
    const float* oth_b0 = (const float*)d_in[6];
    const float* oth_w1 = (const float*)d_in[7];
    const float* oth_b1 = (const float*)d_in[8];
    const float* Wk     = (const float*)d_in[9];
    const float* Wv     = (const float*)d_in[10];
    const float* Wq     = (const float*)d_in[11];
    const float* Wc     = (const float*)d_in[12];
    float* out = (float*)d_out;

    prep_weights<<<16, 256>>>(oth_w0, oth_w1, Wk, Wv);
    ego_attn_kernel<<<8192, NTHR>>>(x, ego_w0, ego_b0, ego_w1, ego_b1,
                                    oth_b0, oth_b1, Wq, Wc, out);
}

// round 9
// speedup vs baseline: 6.2534x; 1.0628x over previous
#include <cuda_runtime.h>
#include <cuda_fp16.h>

// EgoAttentionNetwork: B=8192, E=64, F_IN=7, D=64, H=4, HD=16
// Round-8 = Round-7 (fp16 weight streams, 171.7us) + k-pair weight packing:
//  - PH4 GEMM: one u64 LDG per 2 k-steps (oth_w1).
//  - PH5 GEMM: one uint4 LDG per 2 k-steps carrying BOTH Wk and Wv.
//  - side mat-vecs (ego_w1, Wq, Wc) fp16 k-pair packed: 32-iter chains.

typedef unsigned long long u64;

#define AST 68
#define NTHR 256
#define FULLMASK 0xffffffffu

__device__ __half  dW0h[448];    // oth_w0 [f][d]
__device__ u64     dW1p[1024];   // oth_w1 packed [kp][dt2]: (k0:d0,d0+1)(k1:d0,d0+1)
__device__ uint4   dKVp[1024];   // [kp][dt2]: Wk(k0), Wv(k0), Wk(k1), Wv(k1) half2 each
__device__ __half2 dW1ep[2048];  // ego_w1 [kp*64+d] = (W[2kp][d], W[2kp+1][d])
__device__ __half2 dWqp[2048];   // Wq same packing
__device__ __half2 dWcp[2048];   // Wc same packing

static __device__ __forceinline__ u64 fma2(u64 a, u64 b, u64 c) {
    u64 d;
    asm("fma.rn.f32x2 %0, %1, %2, %3;" : "=l"(d) : "l"(a), "l"(b), "l"(c));
    return d;
}
static __device__ __forceinline__ u64 dup2(float x) {
    u64 r;
    asm("mov.b64 %0, {%1, %1};" : "=l"(r) : "f"(x));
    return r;
}
static __device__ __forceinline__ float2 unpack2(u64 v) {
    float2 r;
    asm("mov.b64 {%0, %1}, %2;" : "=f"(r.x), "=f"(r.y) : "l"(v));
    return r;
}
static __device__ __forceinline__ void loadA(const float* p, u64& a, u64& b) {
    float4 v = *reinterpret_cast<const float4*>(p);
    asm("mov.b64 %0, {%1, %2};" : "=l"(a) : "f"(v.x), "f"(v.y));
    asm("mov.b64 %0, {%1, %2};" : "=l"(b) : "f"(v.z), "f"(v.w));
}
static __device__ __forceinline__ float2 h2f(unsigned int u) {
    __half2 h = *reinterpret_cast<__half2*>(&u);
    return __half22float2(h);
}
static __device__ __forceinline__ unsigned int f2h2(float a, float b) {
    __half2 h = __floats2half2_rn(a, b);
    return *reinterpret_cast<unsigned int*>(&h);
}

__global__ void prep_weights(const float* __restrict__ oth_w0,
                             const float* __restrict__ oth_w1,
                             const float* __restrict__ Wk,
                             const float* __restrict__ Wv,
                             const float* __restrict__ ego_w1,
                             const float* __restrict__ Wq,
                             const float* __restrict__ Wc)
{
    const int i = blockIdx.x * 256 + threadIdx.x;   // 0..2047
    if (i < 448) dW0h[i] = __float2half(__ldg(oth_w0 + i));
    if (i < 1024) {
        const int kp = i >> 5, dt2 = i & 31, d0 = dt2 * 2;
        const int k0 = 2 * kp * 64 + d0, k1 = (2 * kp + 1) * 64 + d0;
        unsigned lo = f2h2(__ldg(oth_w1 + k0), __ldg(oth_w1 + k0 + 1));
        unsigned hi = f2h2(__ldg(oth_w1 + k1), __ldg(oth_w1 + k1 + 1));
        dW1p[i] = (u64)lo | ((u64)hi << 32);
        uint4 kv;
        kv.x = f2h2(__ldg(Wk + k0), __ldg(Wk + k0 + 1));
        kv.y = f2h2(__ldg(Wv + k0), __ldg(Wv + k0 + 1));
        kv.z = f2h2(__ldg(Wk + k1), __ldg(Wk + k1 + 1));
        kv.w = f2h2(__ldg(Wv + k1), __ldg(Wv + k1 + 1));
        dKVp[i] = kv;
    }
    {
        const int kp = i >> 6, d = i & 63;
        const int k0 = 2 * kp * 64 + d, k1 = (2 * kp + 1) * 64 + d;
        dW1ep[i] = __floats2half2_rn(__ldg(ego_w1 + k0), __ldg(ego_w1 + k1));
        dWqp[i]  = __floats2half2_rn(__ldg(Wq + k0),     __ldg(Wq + k1));
        dWcp[i]  = __floats2half2_rn(__ldg(Wc + k0),     __ldg(Wc + k1));
    }
}

struct __align__(16) SmemT {
    float hT[64 * AST];   // hidden^T; reused as V^T after layer1
    float aT[64 * AST];   // input_all^T
    float sX[64 * 8];
    float h0[64];
    float sEgo[64];
    float sQ[64];
    float sO[64];
    float sS[256];
    float sP[256];
    int   sIdx[64];
    int   nOth, uniformF, egoAct;
};

__global__ void __launch_bounds__(NTHR, 4)
ego_attn_kernel(const float* __restrict__ x,
                const float* __restrict__ ego_w0, const float* __restrict__ ego_b0,
                const float* __restrict__ ego_b1,
                const float* __restrict__ oth_b0, const float* __restrict__ oth_b1,
                float* __restrict__ out)
{
    __shared__ SmemT s;
    const int tid = threadIdx.x;
    const int b = blockIdx.x;
    const int dt2 = tid & 31;
    const int d0 = dt2 * 2;
    const int etw = tid >> 5;
    const int etr = (etw + (b & 7)) & 7;
    const float* xb = x + b * 448;
    const __half2* W0h2 = reinterpret_cast<const __half2*>(dW0h);

    // ---- PH1: load x, init scores ----
    for (int idx = tid; idx < 448; idx += NTHR) {
        int e = idx / 7, f = idx % 7;
        s.sX[e * 8 + f] = __ldg(xb + idx);
    }
    s.sS[tid] = -1e30f;
    __syncthreads();

    // ---- PH2: compaction (warp0) | ego layer0 (warp1) ----
    if (tid < 32) {
        const int lane = tid;
        int egoA = (s.sX[0] >= 0.5f) ? 1 : 0;
        unsigned m1 = __ballot_sync(FULLMASK, (lane >= 1) && (s.sX[lane * 8] >= 0.5f));
        unsigned m2 = __ballot_sync(FULLMASK, s.sX[(lane + 32) * 8] >= 0.5f);
        int cnt = __popc(m1) + __popc(m2);
        unsigned lmask = (1u << lane) - 1u;
        if (cnt == 0 && !egoA) {
            s.sIdx[lane] = lane + 1;
            if (lane < 31) s.sIdx[lane + 32] = lane + 33;
            if (lane == 0) { s.nOth = 63; s.uniformF = 1; s.egoAct = egoA; }
        } else {
            if ((lane >= 1) && (m1 >> lane & 1u))
                s.sIdx[__popc(m1 & lmask)] = lane;
            if (m2 >> lane & 1u)
                s.sIdx[__popc(m1) + __popc(m2 & lmask)] = lane + 32;
            if (lane == 0) { s.nOth = cnt; s.uniformF = 0; s.egoAct = egoA; }
        }
    } else if (tid < 64) {
        const int lane = tid - 32;
        #pragma unroll
        for (int r = 0; r < 2; r++) {
            int d = lane + r * 32;
            float acc = __ldg(ego_b0 + d);
            #pragma unroll
            for (int f = 0; f < 7; f++)
                acc += s.sX[f] * __ldg(ego_w0 + f * 64 + d);
            s.h0[d] = fmaxf(acc, 0.f);
        }
    }
    __syncthreads();

    const int nOth = s.nOth;
    const int uniformF = s.uniformF;
    const int egoAct = s.egoAct;
    const int cEgo = nOth;
    const int nTot = nOth + 1;
    int PADMAX = (nTot + 3) & ~3; if (PADMAX > 64) PADMAX = 64;
    const int nTiles = PADMAX >> 2;
    const int npass = (PADMAX + 31) >> 5;

    // ---- PH3: others layer0 (192 thr) | ego layer1 (64 thr, packed fp16) ----
    if (tid < 192) {
        const int total = nOth * 32;
        for (int idx = tid; idx < total; idx += 192) {
            int i = idx >> 5, dd = (idx & 31) * 2;
            int e = s.sIdx[i];
            const float* xr = s.sX + e * 8;
            float2 bb = *reinterpret_cast<const float2*>(oth_b0 + dd);
            float ax = bb.x, ay = bb.y;
            #pragma unroll
            for (int f = 0; f < 7; f++) {
                float2 w = __half22float2(W0h2[f * 32 + (dd >> 1)]);
                float xv = xr[f];
                ax += xv * w.x; ay += xv * w.y;
            }
            s.hT[dd * AST + i]       = fmaxf(ax, 0.f);
            s.hT[(dd + 1) * AST + i] = fmaxf(ay, 0.f);
        }
    } else {
        const int d = tid - 192;
        float a0 = __ldg(ego_b1 + d), a1 = 0.f;
        #pragma unroll 8
        for (int kp = 0; kp < 32; kp++) {
            float2 w = __half22float2(__ldg(&dW1ep[kp * 64 + d]));
            float2 hv = *reinterpret_cast<const float2*>(&s.h0[2 * kp]);
            a0 += hv.x * w.x;
            a1 += hv.y * w.y;
        }
        s.sEgo[d] = fmaxf(a0 + a1, 0.f);
    }
    if (tid < 64) {
        for (int c = nOth; c < PADMAX; c++) s.hT[tid * AST + c] = 0.f;
    }
    __syncthreads();

    // ---- PH4: layer1 GEMM hT->aT (k-pair packed weights); free warps: q ----
    for (int ep = 0; ep < npass; ep++) {
        const int e0 = ep * 32 + etr * 4;
        if (e0 < PADMAX) {
            u64 a00 = 0, a01 = 0, a10 = 0, a11 = 0;
            #pragma unroll 4
            for (int kp = 0; kp < 32; kp++) {
                u64 wp = __ldg(&dW1p[kp * 32 + dt2]);
                float2 wA = h2f((unsigned)wp);
                float2 wB = h2f((unsigned)(wp >> 32));
                u64 p01, p23;
                loadA(s.hT + (2 * kp) * AST + e0, p01, p23);
                u64 wx = dup2(wA.x), wy = dup2(wA.y);
                a00 = fma2(p01, wx, a00);  a01 = fma2(p23, wx, a01);
                a10 = fma2(p01, wy, a10);  a11 = fma2(p23, wy, a11);
                loadA(s.hT + (2 * kp + 1) * AST + e0, p01, p23);
                wx = dup2(wB.x); wy = dup2(wB.y);
                a00 = fma2(p01, wx, a00);  a01 = fma2(p23, wx, a01);
                a10 = fma2(p01, wy, a10);  a11 = fma2(p23, wy, a11);
            }
            float b0v = __ldg(oth_b1 + d0);
            float b1v = __ldg(oth_b1 + d0 + 1);
            float2 c0 = unpack2(a00), c1 = unpack2(a01);
            float2 c2 = unpack2(a10), c3 = unpack2(a11);
            float r0[4] = { fmaxf(c0.x + b0v, 0.f), fmaxf(c0.y + b0v, 0.f),
                            fmaxf(c1.x + b0v, 0.f), fmaxf(c1.y + b0v, 0.f) };
            float r1[4] = { fmaxf(c2.x + b1v, 0.f), fmaxf(c2.y + b1v, 0.f),
                            fmaxf(c3.x + b1v, 0.f), fmaxf(c3.y + b1v, 0.f) };
            const int patch = cEgo - e0;
            if (patch >= 0 && patch < 4) {
                r0[patch] = s.sEgo[d0];
                r1[patch] = s.sEgo[d0 + 1];
            }
            *reinterpret_cast<float4*>(s.aT + d0 * AST + e0) =
                make_float4(r0[0], r0[1], r0[2], r0[3]);
            *reinterpret_cast<float4*>(s.aT + (d0 + 1) * AST + e0) =
                make_float4(r1[0], r1[1], r1[2], r1[3]);
        }
    }
    const bool canFreeQ = (nTiles <= 6);
    if (canFreeQ && etr >= nTiles && (etr - nTiles) < 2) {
        const int d = (etr - nTiles) * 32 + dt2;
        float a0 = 0.f, a1 = 0.f;
        #pragma unroll 8
        for (int kp = 0; kp < 32; kp++) {
            float2 w = __half22float2(__ldg(&dWqp[kp * 64 + d]));
            float2 ev = *reinterpret_cast<const float2*>(&s.sEgo[2 * kp]);
            a0 += ev.x * w.x;
            a1 += ev.y * w.y;
        }
        s.sQ[d] = a0 + a1;
    }
    __syncthreads();
    if (!canFreeQ) {
        if (tid < 64) {
            const int d = tid;
            float a0 = 0.f, a1 = 0.f;
            #pragma unroll 8
            for (int kp = 0; kp < 32; kp++) {
                float2 w = __half22float2(__ldg(&dWqp[kp * 64 + d]));
                float2 ev = *reinterpret_cast<const float2*>(&s.sEgo[2 * kp]);
                a0 += ev.x * w.x;
                a1 += ev.y * w.y;
            }
            s.sQ[d] = a0 + a1;
        }
        __syncthreads();
    }

    // ---- PH5: fused K+V GEMM (one uint4 per 2k); scores via shfl; V^T -> hT ----
    for (int ep = 0; ep < npass; ep++) {
        const int e0 = ep * 32 + etr * 4;
        if (e0 < PADMAX) {
            u64 k00 = 0, k01 = 0, k10 = 0, k11 = 0;
            u64 v00 = 0, v01 = 0, v10 = 0, v11 = 0;
            #pragma unroll 4
            for (int kp = 0; kp < 32; kp++) {
                uint4 kv = __ldg(&dKVp[kp * 32 + dt2]);
                float2 wk0 = h2f(kv.x), wv0 = h2f(kv.y);
                float2 wk1 = h2f(kv.z), wv1 = h2f(kv.w);
                u64 p01, p23;
                loadA(s.aT + (2 * kp) * AST + e0, p01, p23);
                u64 kx = dup2(wk0.x), ky = dup2(wk0.y);
                u64 vx = dup2(wv0.x), vy = dup2(wv0.y);
                k00 = fma2(p01, kx, k00);  k01 = fma2(p23, kx, k01);
                k10 = fma2(p01, ky, k10);  k11 = fma2(p23, ky, k11);
                v00 = fma2(p01, vx, v00);  v01 = fma2(p23, vx, v01);
                v10 = fma2(p01, vy, v10);  v11 = fma2(p23, vy, v11);
                loadA(s.aT + (2 * kp + 1) * AST + e0, p01, p23);
                kx = dup2(wk1.x); ky = dup2(wk1.y);
                vx = dup2(wv1.x); vy = dup2(wv1.y);
                k00 = fma2(p01, kx, k00);  k01 = fma2(p23, kx, k01);
                k10 = fma2(p01, ky, k10);  k11 = fma2(p23, ky, k11);
                v00 = fma2(p01, vx, v00);  v01 = fma2(p23, vx, v01);
                v10 = fma2(p01, vy, v10);  v11 = fma2(p23, vy, v11);
            }
            u64 q0 = dup2(s.sQ[d0]), q1 = dup2(s.sQ[d0 + 1]);
            u64 s01 = fma2(k00, q0, (u64)0), s23 = fma2(k01, q0, (u64)0);
            s01 = fma2(k10, q1, s01);        s23 = fma2(k11, q1, s23);
            float2 f01 = unpack2(s01), f23 = unpack2(s23);
            float sc0 = f01.x, sc1 = f01.y, sc2 = f23.x, sc3 = f23.y;
            #pragma unroll
            for (int o = 1; o < 8; o <<= 1) {
                sc0 += __shfl_xor_sync(FULLMASK, sc0, o);
                sc1 += __shfl_xor_sync(FULLMASK, sc1, o);
                sc2 += __shfl_xor_sync(FULLMASK, sc2, o);
                sc3 += __shfl_xor_sync(FULLMASK, sc3, o);
            }
            if ((dt2 & 7) == 0) {
                const int h = dt2 >> 3;
                float scv[4] = {sc0, sc1, sc2, sc3};
                #pragma unroll
                for (int m = 0; m < 4; m++) {
                    int col = e0 + m;
                    bool act = uniformF ? (col < nTot)
                                        : ((col < nOth) || (col == cEgo && egoAct));
                    s.sS[h * 64 + col] = act ? scv[m] * 0.25f : -1e30f;
                }
            }
            float2 va = unpack2(v00), vb = unpack2(v01);
            *reinterpret_cast<float4*>(s.hT + d0 * AST + e0) =
                make_float4(va.x, va.y, vb.x, vb.y);
            float2 vc = unpack2(v10), vd = unpack2(v11);
            *reinterpret_cast<float4*>(s.hT + (d0 + 1) * AST + e0) =
                make_float4(vc.x, vc.y, vd.x, vd.y);
        }
    }
    __syncthreads();

    // ---- PH6: softmax per head (warps 0-3) ----
    if (tid < 128) {
        const int h = tid >> 5, lane = tid & 31;
        if (uniformF) {
            const float p = 1.0f / 64.0f;
            s.sP[h * 64 + lane] = p;
            s.sP[h * 64 + lane + 32] = p;
        } else {
            float s0 = s.sS[h * 64 + lane];
            float s1 = s.sS[h * 64 + lane + 32];
            float m = fmaxf(s0, s1);
            #pragma unroll
            for (int off = 16; off; off >>= 1)
                m = fmaxf(m, __shfl_xor_sync(FULLMASK, m, off));
            float e0v = __expf(s0 - m);
            float e1v = __expf(s1 - m);
            float sum = e0v + e1v;
            #pragma unroll
            for (int off = 16; off; off >>= 1)
                sum += __shfl_xor_sync(FULLMASK, sum, off);
            float inv = 1.0f / sum;
            s.sP[h * 64 + lane] = e0v * inv;
            s.sP[h * 64 + lane + 32] = e1v * inv;
        }
    }
    __syncthreads();

    // ---- PH7: attention-weighted sum from V^T ----
    if (tid < 64) {
        const int d = tid, h = d >> 4;
        const float* pr = s.sP + h * 64;
        const float* vr = s.hT + d * AST;
        float a0 = 0.f, a1 = 0.f;
        for (int i = 0; i < PADMAX; i += 4) {
            float4 v = *reinterpret_cast<const float4*>(vr + i);
            a0 += pr[i] * v.x + pr[i + 1] * v.y;
            a1 += pr[i + 2] * v.z + pr[i + 3] * v.w;
        }
        s.sO[d] = a0 + a1;
    }
    __syncthreads();

    // ---- PH8: epilogue (out @ Wc + ego) * 0.5, packed fp16 Wc ----
    if (tid < 64) {
        const int d = tid;
        float a0 = 0.f, a1 = 0.f;
        #pragma unroll 8
        for (int kp = 0; kp < 32; kp++) {
            float2 w = __half22float2(__ldg(&dWcp[kp * 64 + d]));
            float2 ov = *reinterpret_cast<const float2*>(&s.sO[2 * kp]);
            a0 += ov.x * w.x;
            a1 += ov.y * w.y;
        }
        out[b * 64 + d] = ((a0 + a1) + s.sEgo[d]) * 0.5f;
    }
}

extern "C" void kernel_launch(void* const* d_in, const int* in_sizes, int n_in,
                              void* d_out, int out_size) {
    (void)in_sizes; (void)n_in; (void)out_size;
    const float* x      = (const float*)d_in[0];
    const float* ego_w0 = (const float*)d_in[1];
    const float* ego_b0 = (const float*)d_in[2];
    const float* ego_w1 = (const float*)d_in[3];
    const float* ego_b1 = (const float*)d_in[4];
    const float* oth_w0 = (const float*)d_in[5];
    const float* oth_b0 = (const float*)d_in[6];
    const float* oth_w1 = (const float*)d_in[7];
    const float* oth_b1 = (const float*)d_in[8];
    const float* Wk     = (const float*)d_in[9];
    const float* Wv     = (const float*)d_in[10];
    const float* Wq     = (const float*)d_in[11];
    const float* Wc     = (const float*)d_in[12];
    float* out = (float*)d_out;

    prep_weights<<<8, 256>>>(oth_w0, oth_w1, Wk, Wv, ego_w1, Wq, Wc);
    ego_attn_kernel<<<8192, NTHR>>>(x, ego_w0, ego_b0, ego_b1,
                                    oth_b0, oth_b1, out);
}